// round 1
// baseline (speedup 1.0000x reference)
#include <cuda_runtime.h>

#define Bsz   2048
#define Ssz   64
#define DSz   128
#define Hsz   512
#define MT    64      // batch rows per CTA
#define NT    128     // N chunk
#define KTm   32      // K tile
#define TH    256
#define XS_LD 132
#define H1_LD 516
#define WT_LD 132
#define NSPIN 32

__device__ float g_ampParts[Ssz * Bsz];
__device__ float g_phase[Bsz];

static __device__ __forceinline__ unsigned long long pk2(float lo, float hi) {
    unsigned long long r;
    asm("mov.b64 %0, {%1, %2};"
        : "=l"(r) : "r"(__float_as_uint(lo)), "r"(__float_as_uint(hi)));
    return r;
}
static __device__ __forceinline__ float2 unpk2(unsigned long long v) {
    unsigned int a, b;
    asm("mov.b64 {%0, %1}, %2;" : "=r"(a), "=r"(b) : "l"(v));
    return make_float2(__uint_as_float(a), __uint_as_float(b));
}
#define FMA2(d, a, b, c) \
    asm("fma.rn.f32x2 %0, %1, %2, %3;" : "=l"(d) : "l"(a), "l"(b), "l"(c))

static __device__ __forceinline__ float silu_f(float v) {
    return v / (1.0f + __expf(-v));
}

struct Acc { unsigned long long v[4][4]; };

static __device__ __forceinline__ void acc_zero(Acc& a) {
#pragma unroll
    for (int i = 0; i < 4; i++)
#pragma unroll
        for (int j = 0; j < 4; j++) a.v[i][j] = 0ull;  // packed (0.f, 0.f)
}

// acc(4 rows x 8 cols, as 4x4 f32x2) += A[arow..arow+3][0..KTm) * Wt[0..KTm)[col..col+7]
static __device__ __forceinline__ void mma_tile(
    Acc& acc, const float* __restrict__ A, int a_ld, int arow,
    const float* __restrict__ Wt, int col)
{
#pragma unroll
    for (int k = 0; k < KTm; k++) {
        float4 b0 = *reinterpret_cast<const float4*>(Wt + k * WT_LD + col);
        float4 b1 = *reinterpret_cast<const float4*>(Wt + k * WT_LD + col + 4);
        unsigned long long bp0 = pk2(b0.x, b0.y);
        unsigned long long bp1 = pk2(b0.z, b0.w);
        unsigned long long bp2 = pk2(b1.x, b1.y);
        unsigned long long bp3 = pk2(b1.z, b1.w);
#pragma unroll
        for (int i = 0; i < 4; i++) {
            float av = A[(arow + i) * a_ld + k];
            unsigned long long aa = pk2(av, av);
            FMA2(acc.v[i][0], aa, bp0, acc.v[i][0]);
            FMA2(acc.v[i][1], aa, bp1, acc.v[i][1]);
            FMA2(acc.v[i][2], aa, bp2, acc.v[i][2]);
            FMA2(acc.v[i][3], aa, bp3, acc.v[i][3]);
        }
    }
}

// load a KTm x NT tile (row-major, leading dim ldW) into Wt smem; Wg already offset
static __device__ __forceinline__ void load_wt(
    float* __restrict__ Wt, const float* __restrict__ Wg, int ldW, int tid)
{
    int c4 = (tid & 31) * 4;
    int r0 = tid >> 5;
#pragma unroll
    for (int m = 0; m < 4; m++) {
        int r = r0 + 8 * m;
        float4 v = *reinterpret_cast<const float4*>(Wg + (size_t)r * ldW + c4);
        *reinterpret_cast<float4*>(Wt + r * WT_LD + c4) = v;
    }
}

static __device__ __forceinline__ void load_x_tile(
    float* __restrict__ Xs, const int* __restrict__ x, int m0, int tid)
{
    int c4 = (tid & 31) * 4;
    int r0 = tid >> 5;
#pragma unroll
    for (int m = 0; m < 8; m++) {
        int r = r0 + 8 * m;
        int4 v = *reinterpret_cast<const int4*>(x + (size_t)(m0 + r) * DSz + c4);
        Xs[r * XS_LD + c4 + 0] = (float)v.x;
        Xs[r * XS_LD + c4 + 1] = (float)v.y;
        Xs[r * XS_LD + c4 + 2] = (float)v.z;
        Xs[r * XS_LD + c4 + 3] = (float)v.w;
    }
}

extern __shared__ float smem[];

// grid: (Bsz/MT, Ssz); one CTA = one (batch-tile, site)
__global__ void __launch_bounds__(TH, 1) amp_kernel(
    const int* __restrict__ x,
    const float* __restrict__ W1, const float* __restrict__ b1,
    const float* __restrict__ W2, const float* __restrict__ b2,
    const float* __restrict__ W3, const float* __restrict__ b3)
{
    float* Xs  = smem;                    // MT x XS_LD (reused as h2 chunk later)
    float* Hs  = Xs + MT * XS_LD;         // MT x H1_LD
    float* Wt  = Hs + MT * H1_LD;         // KTm x WT_LD
    float* W3s = Wt + KTm * WT_LD;        // Hsz*4
    float* Ls  = W3s + Hsz * 4;           // MT*4

    const int tid = threadIdx.x;
    const int m0  = blockIdx.x * MT;
    const int s   = blockIdx.y;

    load_x_tile(Xs, x, m0, tid);
    for (int i = tid; i < Hsz * 4; i += TH) W3s[i] = W3[(size_t)s * Hsz * 4 + i];
    __syncthreads();

    // autoregressive prefix counts + occupied bits at site s (threads 0..63)
    int up_e = 0, dn_e = 0, bu = 0, bd = 0;
    if (tid < MT) {
        const float* row = Xs + tid * XS_LD;
        for (int i = 0; i < s; i++) {
            up_e += (int)row[2 * i];
            dn_e += (int)row[2 * i + 1];
        }
        bu = (int)row[2 * s];
        bd = (int)row[2 * s + 1];
    }

    const int arow = (tid >> 4) * 4;
    const int col  = (tid & 15) * 8;

    // ---- layer 1: Hs = silu(Xs @ W1[s] + b1[s]); rows d >= 2s of W1 are zero ----
    const float* W1s = W1 + (size_t)s * DSz * Hsz;
    const int nkt1 = (2 * s + KTm - 1) / KTm;
    for (int nc = 0; nc < Hsz / NT; nc++) {
        Acc acc; acc_zero(acc);
        for (int kt = 0; kt < nkt1; kt++) {
            __syncthreads();
            load_wt(Wt, W1s + (size_t)(kt * KTm) * Hsz + nc * NT, Hsz, tid);
            __syncthreads();
            mma_tile(acc, Xs, XS_LD, arow, Wt, col);
        }
#pragma unroll
        for (int i = 0; i < 4; i++)
#pragma unroll
            for (int j = 0; j < 4; j++) {
                float2 p = unpk2(acc.v[i][j]);
                int c = nc * NT + col + 2 * j;
                Hs[(arow + i) * H1_LD + c]     = silu_f(p.x + b1[(size_t)s * Hsz + c]);
                Hs[(arow + i) * H1_LD + c + 1] = silu_f(p.y + b1[(size_t)s * Hsz + c + 1]);
            }
    }

    // ---- layer 2 (+ fused layer 3): logits[64][4] ----
    const float* W2s = W2 + (size_t)s * Hsz * Hsz;
    const int lrow = tid >> 2, lo = tid & 3;
    float lg = b3[s * 4 + lo];
    for (int nc = 0; nc < Hsz / NT; nc++) {
        Acc acc; acc_zero(acc);
        for (int kt = 0; kt < Hsz / KTm; kt++) {
            __syncthreads();
            load_wt(Wt, W2s + (size_t)(kt * KTm) * Hsz + nc * NT, Hsz, tid);
            __syncthreads();
            mma_tile(acc, Hs, H1_LD, arow, Wt, col);
        }
        // h2 chunk -> Xs (safe: Xs reads done; prev GEMM3 reads fenced by kt-loop barriers)
#pragma unroll
        for (int i = 0; i < 4; i++)
#pragma unroll
            for (int j = 0; j < 4; j++) {
                float2 p = unpk2(acc.v[i][j]);
                int c = nc * NT + col + 2 * j;
                Xs[(arow + i) * XS_LD + col + 2 * j]     = silu_f(p.x + b2[(size_t)s * Hsz + c]);
                Xs[(arow + i) * XS_LD + col + 2 * j + 1] = silu_f(p.y + b2[(size_t)s * Hsz + c + 1]);
            }
        __syncthreads();
        float sum = 0.f;
        for (int k = 0; k < NT; k++)
            sum += Xs[lrow * XS_LD + k] * W3s[(nc * NT + k) * 4 + lo];
        lg += sum;
    }
    Ls[lrow * 4 + lo] = lg;
    __syncthreads();

    // ---- mask + 0.5*logsumexp(2x) + gather ----
    if (tid < MT) {
        float l0 = Ls[tid * 4 + 0], l1 = Ls[tid * 4 + 1];
        float l2 = Ls[tid * 4 + 2], l3 = Ls[tid * 4 + 3];
        const float NEG = -1e30f;
        bool au0 = (s - up_e) < (Ssz - NSPIN);
        bool au1 = up_e < NSPIN;
        bool ad0 = (s - dn_e) < (Ssz - NSPIN);
        bool ad1 = dn_e < NSPIN;
        float d0 = (au0 && ad0) ? l0 : NEG;
        float d1 = (au0 && ad1) ? l1 : NEG;
        float d2 = (au1 && ad0) ? l2 : NEG;
        float d3 = (au1 && ad1) ? l3 : NEG;
        float mx = fmaxf(fmaxf(d0, d1), fmaxf(d2, d3));
        float sum = expf(2.f * (d0 - mx)) + expf(2.f * (d1 - mx))
                  + expf(2.f * (d2 - mx)) + expf(2.f * (d3 - mx));
        float lse = mx + 0.5f * logf(sum);
        int idx = bu * 2 + bd;
        float dsel = (idx == 0) ? d0 : (idx == 1) ? d1 : (idx == 2) ? d2 : d3;
        g_ampParts[s * Bsz + m0 + tid] = dsel - lse;
    }
}

// grid: (Bsz/MT); phase MLP, same tiling
__global__ void __launch_bounds__(TH, 1) phase_kernel(
    const int* __restrict__ x,
    const float* __restrict__ Wp1, const float* __restrict__ bp1,
    const float* __restrict__ Wp2, const float* __restrict__ bp2,
    const float* __restrict__ Wp3, const float* __restrict__ bp3)
{
    float* Xs = smem;                 // MT x XS_LD (reused as h2 chunk)
    float* Hs = Xs + MT * XS_LD;      // MT x H1_LD
    float* Wt = Hs + MT * H1_LD;      // KTm x WT_LD

    const int tid = threadIdx.x;
    const int m0  = blockIdx.x * MT;

    load_x_tile(Xs, x, m0, tid);
    __syncthreads();

    const int arow = (tid >> 4) * 4;
    const int col  = (tid & 15) * 8;

    for (int nc = 0; nc < Hsz / NT; nc++) {
        Acc acc; acc_zero(acc);
        for (int kt = 0; kt < DSz / KTm; kt++) {
            __syncthreads();
            load_wt(Wt, Wp1 + (size_t)(kt * KTm) * Hsz + nc * NT, Hsz, tid);
            __syncthreads();
            mma_tile(acc, Xs, XS_LD, arow, Wt, col);
        }
#pragma unroll
        for (int i = 0; i < 4; i++)
#pragma unroll
            for (int j = 0; j < 4; j++) {
                float2 p = unpk2(acc.v[i][j]);
                int c = nc * NT + col + 2 * j;
                Hs[(arow + i) * H1_LD + c]     = silu_f(p.x + bp1[c]);
                Hs[(arow + i) * H1_LD + c + 1] = silu_f(p.y + bp1[c + 1]);
            }
    }

    float lg = (tid < MT) ? bp3[0] : 0.f;
    for (int nc = 0; nc < Hsz / NT; nc++) {
        Acc acc; acc_zero(acc);
        for (int kt = 0; kt < Hsz / KTm; kt++) {
            __syncthreads();
            load_wt(Wt, Wp2 + (size_t)(kt * KTm) * Hsz + nc * NT, Hsz, tid);
            __syncthreads();
            mma_tile(acc, Hs, H1_LD, arow, Wt, col);
        }
#pragma unroll
        for (int i = 0; i < 4; i++)
#pragma unroll
            for (int j = 0; j < 4; j++) {
                float2 p = unpk2(acc.v[i][j]);
                int c = nc * NT + col + 2 * j;
                Xs[(arow + i) * XS_LD + col + 2 * j]     = silu_f(p.x + bp2[c]);
                Xs[(arow + i) * XS_LD + col + 2 * j + 1] = silu_f(p.y + bp2[c + 1]);
            }
        __syncthreads();
        if (tid < MT) {
            float sum = 0.f;
            for (int k = 0; k < NT; k++)
                sum += Xs[tid * XS_LD + k] * Wp3[nc * NT + k];
            lg += sum;
        }
    }
    if (tid < MT) g_phase[m0 + tid] = lg;
}

__global__ void final_kernel(float2* __restrict__ out) {
    int b = blockIdx.x * blockDim.x + threadIdx.x;
    if (b >= Bsz) return;
    float amp = 0.f;
#pragma unroll 8
    for (int s = 0; s < Ssz; s++) amp += g_ampParts[s * Bsz + b];
    float ea = expf(amp);
    float sv, cv;
    sincosf(g_phase[b], &sv, &cv);
    out[b] = make_float2(ea * cv, ea * sv);
}

extern "C" void kernel_launch(void* const* d_in, const int* in_sizes, int n_in,
                              void* d_out, int out_size)
{
    (void)in_sizes; (void)n_in; (void)out_size;
    const int*   x   = (const int*)  d_in[0];
    const float* W1  = (const float*)d_in[1];
    const float* b1  = (const float*)d_in[2];
    const float* W2  = (const float*)d_in[3];
    const float* b2  = (const float*)d_in[4];
    const float* W3  = (const float*)d_in[5];
    const float* b3  = (const float*)d_in[6];
    const float* Wp1 = (const float*)d_in[7];
    const float* bp1 = (const float*)d_in[8];
    const float* Wp2 = (const float*)d_in[9];
    const float* bp2 = (const float*)d_in[10];
    const float* Wp3 = (const float*)d_in[11];
    const float* bp3 = (const float*)d_in[12];

    const int SMEM_AMP = (MT * XS_LD + MT * H1_LD + KTm * WT_LD + Hsz * 4 + MT * 4) * (int)sizeof(float);
    const int SMEM_PH  = (MT * XS_LD + MT * H1_LD + KTm * WT_LD) * (int)sizeof(float);
    cudaFuncSetAttribute(amp_kernel,   cudaFuncAttributeMaxDynamicSharedMemorySize, SMEM_AMP);
    cudaFuncSetAttribute(phase_kernel, cudaFuncAttributeMaxDynamicSharedMemorySize, SMEM_PH);

    amp_kernel<<<dim3(Bsz / MT, Ssz), TH, SMEM_AMP>>>(x, W1, b1, W2, b2, W3, b3);
    phase_kernel<<<Bsz / MT, TH, SMEM_PH>>>(x, Wp1, bp1, Wp2, bp2, Wp3, bp3);
    final_kernel<<<Bsz / 256, 256>>>((float2*)d_out);
}

// round 3
// speedup vs baseline: 1.4162x; 1.4162x over previous
#include <cuda_runtime.h>

#define Bsz   2048
#define Ssz   64
#define DSz   128
#define Hsz   512
#define MT    64      // batch rows per CTA
#define NT    128     // N chunk
#define KT    32      // K tile
#define TH    128
#define XLD   132
#define HLD   516
#define WLD   132
#define NSPIN 32

__device__ float g_ampParts[Ssz * Bsz];
__device__ float g_phase[Bsz];

static __device__ __forceinline__ unsigned long long pk2(float lo, float hi) {
    unsigned long long r;
    asm("mov.b64 %0, {%1, %2};"
        : "=l"(r) : "r"(__float_as_uint(lo)), "r"(__float_as_uint(hi)));
    return r;
}
static __device__ __forceinline__ float2 unpk2(unsigned long long v) {
    unsigned int a, b;
    asm("mov.b64 {%0, %1}, %2;" : "=r"(a), "=r"(b) : "l"(v));
    return make_float2(__uint_as_float(a), __uint_as_float(b));
}
#define FMA2(d, a, b, c) \
    asm("fma.rn.f32x2 %0, %1, %2, %3;" : "=l"(d) : "l"(a), "l"(b), "l"(c))

static __device__ __forceinline__ float silu_f(float v) {
    return v / (1.0f + __expf(-v));
}

struct AccT { unsigned long long v[8][4]; };

// async-copy one KT x NT weight tile (global row-major, ld = Hsz) into smem buf
static __device__ __forceinline__ void load_tile_async(
    float* dst, const float* __restrict__ src, int tid)
{
#pragma unroll
    for (int j = 0; j < 8; j++) {
        int t = j * TH + tid;
        int row = t >> 5, chunk = t & 31;          // 32 x 16B chunks per 128-float row
        const float* g = src + (size_t)row * Hsz + chunk * 4;
        unsigned sa = (unsigned)__cvta_generic_to_shared(dst + row * WLD + chunk * 4);
        asm volatile("cp.async.cg.shared.global [%0], [%1], 16;" :: "r"(sa), "l"(g));
    }
}

// acc(8x8) += As[r0..r0+7][:] @ Wg[:][c0..c0+7], K = nkt*KT, double-buffered cp.async
static __device__ __forceinline__ void gemm_chunk(
    AccT& acc, const float* __restrict__ As, int ald,
    const float* __restrict__ Wg,   // global W + nc*NT, row stride Hsz
    float* Wt,                       // smem: 2 buffers of KT*WLD
    int nkt, int tid, int r0, int c0)
{
#pragma unroll
    for (int i = 0; i < 8; i++)
#pragma unroll
        for (int j = 0; j < 4; j++) acc.v[i][j] = 0ull;
    if (nkt <= 0) return;

    load_tile_async(Wt, Wg, tid);
    asm volatile("cp.async.commit_group;");

    for (int kt = 0; kt < nkt; kt++) {
        const float* cur = Wt + (kt & 1) * (KT * WLD);
        if (kt + 1 < nkt) {
            load_tile_async(Wt + ((kt + 1) & 1) * (KT * WLD),
                            Wg + (size_t)(kt + 1) * KT * Hsz, tid);
            asm volatile("cp.async.commit_group;");
            asm volatile("cp.async.wait_group 1;");
        } else {
            asm volatile("cp.async.wait_group 0;");
        }
        __syncthreads();
#pragma unroll 8
        for (int k = 0; k < KT; k++) {
            const float* w = cur + k * WLD + c0;
            float4 b0 = *reinterpret_cast<const float4*>(w);
            float4 b1 = *reinterpret_cast<const float4*>(w + 4);
            unsigned long long bp0 = pk2(b0.x, b0.y);
            unsigned long long bp1 = pk2(b0.z, b0.w);
            unsigned long long bp2 = pk2(b1.x, b1.y);
            unsigned long long bp3 = pk2(b1.z, b1.w);
#pragma unroll
            for (int i = 0; i < 8; i++) {
                float av = As[(r0 + i) * ald + k];
                unsigned long long aa = pk2(av, av);
                FMA2(acc.v[i][0], aa, bp0, acc.v[i][0]);
                FMA2(acc.v[i][1], aa, bp1, acc.v[i][1]);
                FMA2(acc.v[i][2], aa, bp2, acc.v[i][2]);
                FMA2(acc.v[i][3], aa, bp3, acc.v[i][3]);
            }
        }
        __syncthreads();
    }
}

extern __shared__ float smem[];

// grid (Bsz/MT, Ssz+1): y<Ssz -> amp site y; y==Ssz -> phase MLP
__global__ void __launch_bounds__(TH, 1) fused_kernel(
    const int* __restrict__ x,
    const float* __restrict__ W1, const float* __restrict__ b1,
    const float* __restrict__ W2, const float* __restrict__ b2,
    const float* __restrict__ W3, const float* __restrict__ b3,
    const float* __restrict__ Wp1, const float* __restrict__ bp1,
    const float* __restrict__ Wp2, const float* __restrict__ bp2,
    const float* __restrict__ Wp3, const float* __restrict__ bp3)
{
    float* Xs  = smem;                  // MT x XLD (x, then h2 chunks)
    float* Hs  = Xs + MT * XLD;         // MT x HLD
    float* Wt  = Hs + MT * HLD;         // 2 x KT x WLD
    float* W3s = Wt + 2 * KT * WLD;     // 512 x 4
    float* Ls  = W3s + Hsz * 4;         // MT x 4

    const int tid = threadIdx.x;
    const int m0  = blockIdx.x * MT;
    const int s   = blockIdx.y;
    const bool isPhase = (s == Ssz);

    // load X tile (row-major) as float
#pragma unroll
    for (int m = 0; m < 16; m++) {
        int t = m * TH + tid;
        int row = t >> 5, c4 = (t & 31) * 4;
        int4 v = *reinterpret_cast<const int4*>(x + (size_t)(m0 + row) * DSz + c4);
        Xs[row * XLD + c4 + 0] = (float)v.x;
        Xs[row * XLD + c4 + 1] = (float)v.y;
        Xs[row * XLD + c4 + 2] = (float)v.z;
        Xs[row * XLD + c4 + 3] = (float)v.w;
    }
    // load W3 (amp) or Wp3 (phase) into W3s [512][4]
    if (!isPhase) {
        const float4* src = reinterpret_cast<const float4*>(W3 + (size_t)s * Hsz * 4);
#pragma unroll
        for (int m = 0; m < 4; m++)
            reinterpret_cast<float4*>(W3s)[m * TH + tid] = src[m * TH + tid];
    } else {
        for (int i = tid; i < Hsz; i += TH) {
            W3s[i * 4 + 0] = Wp3[i];
            W3s[i * 4 + 1] = 0.f; W3s[i * 4 + 2] = 0.f; W3s[i * 4 + 3] = 0.f;
        }
    }
    __syncthreads();

    // autoregressive prefix counts + occupied bits (amp only, into registers)
    int up_e = 0, dn_e = 0, bu = 0, bd = 0;
    if (!isPhase && tid < MT) {
        const float* row = Xs + tid * XLD;
        for (int i = 0; i < s; i++) {
            up_e += (int)row[2 * i];
            dn_e += (int)row[2 * i + 1];
        }
        bu = (int)row[2 * s];
        bd = (int)row[2 * s + 1];
    }

    const int r0 = (tid >> 4) * 8;
    const int c0 = (tid & 15) * 8;

    const float* W1p = isPhase ? Wp1 : W1 + (size_t)s * DSz * Hsz;
    const float* b1p = isPhase ? bp1 : b1 + (size_t)s * Hsz;
    const float* W2p = isPhase ? Wp2 : W2 + (size_t)s * Hsz * Hsz;
    const float* b2p = isPhase ? bp2 : b2 + (size_t)s * Hsz;
    const int nkt1 = isPhase ? (DSz / KT) : (2 * s + KT - 1) / KT;

    // ---- layer 1: Hs = silu(Xs @ W1p + b1p) ----
    for (int nc = 0; nc < Hsz / NT; nc++) {
        AccT acc;
        gemm_chunk(acc, Xs, XLD, W1p + nc * NT, Wt, nkt1, tid, r0, c0);
#pragma unroll
        for (int i = 0; i < 8; i++)
#pragma unroll
            for (int j = 0; j < 4; j++) {
                float2 p = unpk2(acc.v[i][j]);
                int c = nc * NT + c0 + 2 * j;
                Hs[(r0 + i) * HLD + c]     = silu_f(p.x + b1p[c]);
                Hs[(r0 + i) * HLD + c + 1] = silu_f(p.y + b1p[c + 1]);
            }
    }

    // ---- layer 2 + fused layer 3 ----
    const int row3 = tid & 63, og = tid >> 6;
    float lg0 = 0.f, lg1 = 0.f;
    for (int nc = 0; nc < Hsz / NT; nc++) {
        AccT acc;
        gemm_chunk(acc, Hs, HLD, W2p + nc * NT, Wt, Hsz / KT, tid, r0, c0);
        // h2 chunk -> Xs (row-major [MT][NT])
#pragma unroll
        for (int i = 0; i < 8; i++)
#pragma unroll
            for (int j = 0; j < 4; j++) {
                float2 p = unpk2(acc.v[i][j]);
                int c = nc * NT + c0 + 2 * j;
                Xs[(r0 + i) * XLD + c0 + 2 * j]     = silu_f(p.x + b2p[c]);
                Xs[(r0 + i) * XLD + c0 + 2 * j + 1] = silu_f(p.y + b2p[c + 1]);
            }
        __syncthreads();
        float s0 = 0.f, s1 = 0.f;
#pragma unroll 8
        for (int k = 0; k < NT; k++) {
            float v = Xs[row3 * XLD + k];
            s0 += v * W3s[(nc * NT + k) * 4 + og * 2];
            s1 += v * W3s[(nc * NT + k) * 4 + og * 2 + 1];
        }
        lg0 += s0; lg1 += s1;
        __syncthreads();
    }
    Ls[row3 * 4 + og * 2]     = lg0;
    Ls[row3 * 4 + og * 2 + 1] = lg1;
    __syncthreads();

    if (tid < MT) {
        if (isPhase) {
            g_phase[m0 + tid] = Ls[tid * 4 + 0] + bp3[0];
        } else {
            float l0 = Ls[tid * 4 + 0] + b3[s * 4 + 0];
            float l1 = Ls[tid * 4 + 1] + b3[s * 4 + 1];
            float l2 = Ls[tid * 4 + 2] + b3[s * 4 + 2];
            float l3 = Ls[tid * 4 + 3] + b3[s * 4 + 3];
            const float NEG = -1e30f;
            bool au0 = (s - up_e) < (Ssz - NSPIN);
            bool au1 = up_e < NSPIN;
            bool ad0 = (s - dn_e) < (Ssz - NSPIN);
            bool ad1 = dn_e < NSPIN;
            float d0 = (au0 && ad0) ? l0 : NEG;
            float d1 = (au0 && ad1) ? l1 : NEG;
            float d2 = (au1 && ad0) ? l2 : NEG;
            float d3 = (au1 && ad1) ? l3 : NEG;
            float mx = fmaxf(fmaxf(d0, d1), fmaxf(d2, d3));
            float sum = expf(2.f * (d0 - mx)) + expf(2.f * (d1 - mx))
                      + expf(2.f * (d2 - mx)) + expf(2.f * (d3 - mx));
            float lse = mx + 0.5f * logf(sum);
            int idx = bu * 2 + bd;
            float dsel = (idx == 0) ? d0 : (idx == 1) ? d1 : (idx == 2) ? d2 : d3;
            g_ampParts[s * Bsz + m0 + tid] = dsel - lse;
        }
    }
}

__global__ void final_kernel(float2* __restrict__ out) {
    int b = blockIdx.x * blockDim.x + threadIdx.x;
    if (b >= Bsz) return;
    float amp = 0.f;
#pragma unroll 8
    for (int s = 0; s < Ssz; s++) amp += g_ampParts[s * Bsz + b];
    float ea = expf(amp);
    float sv, cv;
    sincosf(g_phase[b], &sv, &cv);
    out[b] = make_float2(ea * cv, ea * sv);
}

extern "C" void kernel_launch(void* const* d_in, const int* in_sizes, int n_in,
                              void* d_out, int out_size)
{
    (void)in_sizes; (void)n_in; (void)out_size;
    const int*   x   = (const int*)  d_in[0];
    const float* W1  = (const float*)d_in[1];
    const float* b1  = (const float*)d_in[2];
    const float* W2  = (const float*)d_in[3];
    const float* b2  = (const float*)d_in[4];
    const float* W3  = (const float*)d_in[5];
    const float* b3  = (const float*)d_in[6];
    const float* Wp1 = (const float*)d_in[7];
    const float* bp1 = (const float*)d_in[8];
    const float* Wp2 = (const float*)d_in[9];
    const float* bp2 = (const float*)d_in[10];
    const float* Wp3 = (const float*)d_in[11];
    const float* bp3 = (const float*)d_in[12];

    const int SMEM = (MT * XLD + MT * HLD + 2 * KT * WLD + Hsz * 4 + MT * 4) * (int)sizeof(float);
    cudaFuncSetAttribute(fused_kernel, cudaFuncAttributeMaxDynamicSharedMemorySize, SMEM);

    fused_kernel<<<dim3(Bsz / MT, Ssz + 1), TH, SMEM>>>(
        x, W1, b1, W2, b2, W3, b3, Wp1, bp1, Wp2, bp2, Wp3, bp3);
    final_kernel<<<Bsz / 256, 256>>>((float2*)d_out);
}